// round 4
// baseline (speedup 1.0000x reference)
#include <cuda_runtime.h>
#include <cuda_bf16.h>

#define N_NODES 384
#define HEIGHT  60
#define CCH     128
#define N_LAYERS 4
#define NODE_SZ (CCH * HEIGHT)          // 7680 floats per node
#define WT_SZ   (CCH * 256)             // 32768 per layer
#define XS_SZ   (CCH * 64)              // 8192 (padded x tile)
#define WS_SZ   (64 * 256)              // 16384 (weight K-chunk)
#define DYN_SMEM ((XS_SZ + WS_SZ) * 4)  // 96 KB

// ---------------- device scratch ----------------
__device__ float g_y[2][N_NODES * 2 * NODE_SZ];       // double-buffered [buf][n][a/b][c][h]
__device__ float g_wt[N_LAYERS * WT_SZ];              // folded weights [l][k][r]
__device__ float g_M[N_LAYERS * CCH * 6];
__device__ int   g_nbr[N_NODES * 16];
__device__ int   g_deg[N_NODES];

// ---------------- setup: block 0 = CSR, blocks 1..4 = weight folding ----------
__global__ void setup_kernel(const int* __restrict__ ei, int E,
                             const float* __restrict__ conv_w,
                             const float* __restrict__ edge_w,
                             const float* __restrict__ edge_b) {
    int tid = threadIdx.x;
    if (blockIdx.x == 0) {
        int n = tid;
        if (n >= N_NODES) return;
        const int* dst = ei + E;
        int cnt = 0;
        for (int e = 0; e < E; e++) {
            if (dst[e] == n) {
                if (cnt < 16) g_nbr[n * 16 + cnt] = e;
                cnt++;
            }
        }
        g_deg[n] = cnt < 16 ? cnt : 16;
        return;
    }
    int l = blockIdx.x - 1;
    const float* cw = conv_w + l * (CCH * 3 * CCH);
    for (int i = tid; i < WT_SZ; i += 384) {
        int k = i >> 8, r = i & 255;
        float v;
        if (r < 128) v = cw[r * 384 + k] - cw[r * 384 + 128 + k];
        else         v = cw[(r - 128) * 384 + 128 + k];
        g_wt[l * WT_SZ + i] = v;
    }
    if (tid < CCH) {
        int c = tid;
        const float* cw3 = cw + c * 384 + 256;
        const float* ewl = edge_w + l * (CCH * 5);
        const float* ebl = edge_b + l * CCH;
        float m0 = 0.f, m1 = 0.f, m2 = 0.f, m3 = 0.f, m4 = 0.f, m5 = 0.f;
        for (int k = 0; k < CCH; k++) {
            float w = cw3[k];
            m0 += w * ewl[k * 5 + 0];
            m1 += w * ewl[k * 5 + 1];
            m2 += w * ewl[k * 5 + 2];
            m3 += w * ewl[k * 5 + 3];
            m4 += w * ewl[k * 5 + 4];
            m5 += w * ebl[k];
        }
        float* Mp = g_M + l * (CCH * 6) + c * 6;
        Mp[0] = m0; Mp[1] = m1; Mp[2] = m2; Mp[3] = m3; Mp[4] = m4; Mp[5] = m5;
    }
}

// ---------------- shared GEMM body: y[n](256x60) = Wt(256x128)@xs(128x60) -----
// xs in smem [128][64]; ws staged per 64-K chunk. Lane owns rows {lane+32r};
// warp owns 8 h-cols. Conflict-free LDS, fp32x2 FMA.
__device__ __forceinline__ void gemm_body(float* xs, float* ws,
                                          const float* __restrict__ wt,
                                          float* __restrict__ yout, int n, int tid) {
    int lane = tid & 31, wid = tid >> 5;
    int h0 = wid << 3;

    unsigned long long acc[8][4];
#pragma unroll
    for (int r = 0; r < 8; r++)
#pragma unroll
        for (int j = 0; j < 4; j++) acc[r][j] = 0ULL;

    for (int kc = 0; kc < 2; kc++) {
        __syncthreads();
        const float* wsrc = wt + kc * (64 * 256);
        for (int i = tid * 4; i < 64 * 256; i += 256 * 4)
            *(float4*)(ws + i) = *(const float4*)(wsrc + i);
        __syncthreads();

#pragma unroll 2
        for (int kk = 0; kk < 64; kk++) {
            int kb = ((kc << 6) + kk) << 6;
            ulonglong2 xv01 = *reinterpret_cast<const ulonglong2*>(xs + kb + h0);
            ulonglong2 xv23 = *reinterpret_cast<const ulonglong2*>(xs + kb + h0 + 4);
            unsigned long long xv[4] = {xv01.x, xv01.y, xv23.x, xv23.y};
            const float* wrow = ws + (kk << 8) + lane;
#pragma unroll
            for (int r = 0; r < 8; r++) {
                float w = wrow[r << 5];
                unsigned long long wp;
                asm("mov.b64 %0, {%1, %2};" : "=l"(wp) : "f"(w), "f"(w));
#pragma unroll
                for (int j = 0; j < 4; j++)
                    asm("fma.rn.f32x2 %0, %1, %2, %0;"
                        : "+l"(acc[r][j]) : "l"(wp), "l"(xv[j]));
            }
        }
    }

#pragma unroll
    for (int r = 0; r < 8; r++) {
        int row = lane + (r << 5);
        float o[8];
#pragma unroll
        for (int j = 0; j < 4; j++)
            asm("mov.b64 {%0, %1}, %2;" : "=f"(o[2 * j]), "=f"(o[2 * j + 1]) : "l"(acc[r][j]));
        float* yp = yout + ((size_t)(n * 2 + (row >> 7))) * NODE_SZ + (row & 127) * HEIGHT + h0;
        *(float4*)yp = make_float4(o[0], o[1], o[2], o[3]);
        if (h0 < 56)
            *(float4*)(yp + 4) = make_float4(o[4], o[5], o[6], o[7]);
    }
}

// ---------------- G0: gemm layer 0 from input x ------------------------------
__global__ __launch_bounds__(256, 2)
void gemm0_kernel(const float* __restrict__ x0) {
    extern __shared__ float sm[];
    float* xs = sm;
    float* ws = sm + XS_SZ;
    int n = blockIdx.x, tid = threadIdx.x;
    const float* xn = x0 + (size_t)n * NODE_SZ;
#pragma unroll 4
    for (int i = tid; i < XS_SZ; i += 256) {
        int k = i >> 6, h = i & 63;
        xs[i] = (h < HEIGHT) ? xn[k * HEIGHT + h] : 0.f;
    }
    gemm_body(xs, ws, g_wt, g_y[0], n, tid);
}

// ---------------- F_l: edge(l) [+ gemm(l+1)] ---------------------------------
// edge: h_e = ya[dst]+yb[src]+es; LN(C,H); relu; accumulate (regs).
// then (l<3): acc -> xs tile, gemm(l+1) -> g_y[(l+1)&1]. (l==3): acc -> dout.
__global__ __launch_bounds__(256, 2)
void fused_kernel(const float* __restrict__ ea,
                  const float* __restrict__ lng,
                  const float* __restrict__ lnb,
                  const int* __restrict__ ei,
                  float* __restrict__ dout, int l) {
    extern __shared__ float sm[];
    float* xs = sm;
    float* ws = sm + XS_SZ;
    float* t  = ws;                      // alias: dead before ws is loaded
    __shared__ float es[CCH];
    __shared__ float red[16];

    int n = blockIdx.x, tid = threadIdx.x;
    const float* gl = lng + l * NODE_SZ;
    const float* bl = lnb + l * NODE_SZ;
    const float* ybuf = g_y[l & 1];
    const float* yan = ybuf + (size_t)(2 * n) * NODE_SZ;

    float ya[30], acc[30];
#pragma unroll
    for (int it = 0; it < 30; it++) {
        ya[it] = yan[tid + (it << 8)];
        acc[it] = 0.f;
    }
    int deg = g_deg[n];

    for (int j = 0; j < deg; j++) {
        int e = g_nbr[n * 16 + j];
        int s = ei[e];
        if (tid < CCH) {
            const float* Mp = g_M + l * (CCH * 6) + tid * 6;
            const float* eap = ea + e * 5;
            es[tid] = fmaf(Mp[0], eap[0], fmaf(Mp[1], eap[1], fmaf(Mp[2], eap[2],
                      fmaf(Mp[3], eap[3], fmaf(Mp[4], eap[4], Mp[5])))));
        }
        __syncthreads();   // es ready; orders t/red reuse across edges

        const float* yb = ybuf + (size_t)(2 * s + 1) * NODE_SZ;
        float s1 = 0.f, s2 = 0.f;
#pragma unroll
        for (int it = 0; it < 30; it++) {
            int i = tid + (it << 8);
            float v = ya[it] + yb[i] + es[i / HEIGHT];
            t[i] = v;
            s1 += v;
            s2 += v * v;
        }
#pragma unroll
        for (int o = 16; o; o >>= 1) {
            s1 += __shfl_xor_sync(0xffffffffu, s1, o);
            s2 += __shfl_xor_sync(0xffffffffu, s2, o);
        }
        int wid = tid >> 5, lane = tid & 31;
        if (lane == 0) { red[wid] = s1; red[8 + wid] = s2; }
        __syncthreads();
        float a = 0.f, b2 = 0.f;
#pragma unroll
        for (int w = 0; w < 8; w++) { a += red[w]; b2 += red[8 + w]; }
        float mu = a * (1.f / (float)NODE_SZ);
        float rs = rsqrtf(b2 * (1.f / (float)NODE_SZ) - mu * mu + 1e-5f);
#pragma unroll
        for (int it = 0; it < 30; it++) {
            int i = tid + (it << 8);
            float v = (t[i] - mu) * rs * gl[i] + bl[i];
            acc[it] += fmaxf(v, 0.f);
        }
    }

    if (l == 3) {
        float* on = dout + (size_t)n * NODE_SZ;
#pragma unroll
        for (int it = 0; it < 30; it++)
            on[tid + (it << 8)] = acc[it];
        return;
    }

    // stage acc into xs as [k][64] (pad cols 60..63 = 0), then gemm(l+1)
    __syncthreads();   // all t reads done before xs/ws reuse
#pragma unroll
    for (int it = 0; it < 30; it++) {
        int i = tid + (it << 8);
        int k = i / HEIGHT, h = i - k * HEIGHT;
        xs[(k << 6) + h] = acc[it];
    }
    // zero pad columns
    for (int p = tid; p < CCH * 4; p += 256) {
        int k = p >> 2;
        xs[(k << 6) + 60 + (p & 3)] = 0.f;
    }
    gemm_body(xs, ws, g_wt + (l + 1) * WT_SZ, g_y[(l + 1) & 1], n, tid);
}

// ---------------- launch -----------------------------------------------------
extern "C" void kernel_launch(void* const* d_in, const int* in_sizes, int n_in,
                              void* d_out, int out_size) {
    const float* x   = (const float*)d_in[0];
    const float* ea  = (const float*)d_in[1];
    const float* ew  = (const float*)d_in[2];
    const float* eb  = (const float*)d_in[3];
    const float* cw  = (const float*)d_in[4];
    const float* lng = (const float*)d_in[5];
    const float* lnb = (const float*)d_in[6];
    const int*   ei  = (const int*)d_in[7];
    float* out = (float*)d_out;
    int E = in_sizes[7] / 2;

    cudaFuncSetAttribute(gemm0_kernel, cudaFuncAttributeMaxDynamicSharedMemorySize, DYN_SMEM);
    cudaFuncSetAttribute(fused_kernel, cudaFuncAttributeMaxDynamicSharedMemorySize, DYN_SMEM);

    setup_kernel<<<5, 384>>>(ei, E, cw, ew, eb);
    gemm0_kernel<<<N_NODES, 256, DYN_SMEM>>>(x);
    for (int l = 0; l < N_LAYERS; l++)
        fused_kernel<<<N_NODES, 256, DYN_SMEM>>>(ea, lng, lnb, ei, out, l);
}

// round 5
// speedup vs baseline: 1.0047x; 1.0047x over previous
#include <cuda_runtime.h>

#define N_NODES 384
#define HEIGHT  60
#define CCH     128
#define N_LAYERS 4
#define NODE_SZ (CCH * HEIGHT)          // 7680 floats per node
#define WT_SZ   (CCH * 256)             // folded weights per layer
#define XS_SZ   (CCH * 64)              // 8192 (padded x tile)
#define ES_OFF  (3 * NODE_SZ)           // 23040
#define DYN_F   (ES_OFF + 8 * CCH)      // 24064 floats = 96256 B
#define DYN_SMEM (DYN_F * 4)
#define G0_SMEM (XS_SZ * 4)

// ---------------- device scratch ----------------
__device__ __align__(16) float g_y[2][N_NODES * 2 * NODE_SZ];
__device__ __align__(16) float g_wt[N_LAYERS * WT_SZ];   // [l][k][r], r in [0,256)
__device__ float g_M[N_LAYERS * CCH * 6];
__device__ int   g_nbr[N_NODES * 16];
__device__ int   g_deg[N_NODES];

// ---------------- cp.async helpers ----------------
__device__ __forceinline__ void cp16(unsigned dst, const float* src) {
    asm volatile("cp.async.cg.shared.global [%0], [%1], 16;" :: "r"(dst), "l"(src));
}
__device__ __forceinline__ void prefetch_node(float* buf, const float* __restrict__ src, int tid) {
    unsigned b = (unsigned)__cvta_generic_to_shared(buf);
    for (int i = tid; i < NODE_SZ / 4; i += 256)
        cp16(b + i * 16, src + i * 4);
    asm volatile("cp.async.commit_group;");
}

// ---------------- setup: block 0 = CSR, blocks 1..4 = weight folding ----------
__global__ void setup_kernel(const int* __restrict__ ei, int E,
                             const float* __restrict__ conv_w,
                             const float* __restrict__ edge_w,
                             const float* __restrict__ edge_b) {
    int tid = threadIdx.x;
    if (blockIdx.x == 0) {
        int n = tid;
        if (n >= N_NODES) return;
        const int* dst = ei + E;
        int cnt = 0;
        for (int e = 0; e < E; e++) {
            if (dst[e] == n) {
                if (cnt < 8) g_nbr[n * 16 + cnt] = e;
                cnt++;
            }
        }
        g_deg[n] = cnt < 8 ? cnt : 8;
        return;
    }
    int l = blockIdx.x - 1;
    const float* cw = conv_w + l * (CCH * 3 * CCH);
    for (int i = tid; i < WT_SZ; i += 384) {
        int k = i >> 8, r = i & 255;
        float v;
        if (r < 128) v = cw[r * 384 + k] - cw[r * 384 + 128 + k];
        else         v = cw[(r - 128) * 384 + 128 + k];
        g_wt[l * WT_SZ + i] = v;
    }
    if (tid < CCH) {
        int c = tid;
        const float* cw3 = cw + c * 384 + 256;
        const float* ewl = edge_w + l * (CCH * 5);
        const float* ebl = edge_b + l * CCH;
        float m0 = 0.f, m1 = 0.f, m2 = 0.f, m3 = 0.f, m4 = 0.f, m5 = 0.f;
        for (int k = 0; k < CCH; k++) {
            float w = cw3[k];
            m0 += w * ewl[k * 5 + 0];
            m1 += w * ewl[k * 5 + 1];
            m2 += w * ewl[k * 5 + 2];
            m3 += w * ewl[k * 5 + 3];
            m4 += w * ewl[k * 5 + 4];
            m5 += w * ebl[k];
        }
        float* Mp = g_M + l * (CCH * 6) + c * 6;
        Mp[0] = m0; Mp[1] = m1; Mp[2] = m2; Mp[3] = m3; Mp[4] = m4; Mp[5] = m5;
    }
}

// ---------------- GEMM body: y[n](256x60) = Wt(256x128) @ xs(128x60) ---------
// Weights streamed from global (L1-resident, shared by all CTAs) via LDG.128.
// Thread owns rows {4*lane+q} (part a) and {128+4*lane+q} (part b), 8 h-cols/warp.
__device__ __forceinline__ void gemm_body(const float* xs,
                                          const float* __restrict__ wt,
                                          float* __restrict__ yout, int n, int tid) {
    int lane = tid & 31, wid = tid >> 5;
    int h0 = wid << 3, r0 = lane << 2;

    unsigned long long acc[2][4][4];
#pragma unroll
    for (int p = 0; p < 2; p++)
#pragma unroll
        for (int q = 0; q < 4; q++)
#pragma unroll
            for (int j = 0; j < 4; j++) acc[p][q][j] = 0ULL;

#pragma unroll 2
    for (int kk = 0; kk < CCH; kk++) {
        ulonglong2 x01 = *reinterpret_cast<const ulonglong2*>(xs + (kk << 6) + h0);
        ulonglong2 x23 = *reinterpret_cast<const ulonglong2*>(xs + (kk << 6) + h0 + 4);
        unsigned long long xv[4] = {x01.x, x01.y, x23.x, x23.y};
        float4 wa = __ldg(reinterpret_cast<const float4*>(wt + (kk << 8) + r0));
        float4 wb = __ldg(reinterpret_cast<const float4*>(wt + (kk << 8) + 128 + r0));
        float wf[2][4] = {{wa.x, wa.y, wa.z, wa.w}, {wb.x, wb.y, wb.z, wb.w}};
#pragma unroll
        for (int p = 0; p < 2; p++)
#pragma unroll
            for (int q = 0; q < 4; q++) {
                unsigned long long wp;
                asm("mov.b64 %0, {%1, %2};" : "=l"(wp) : "f"(wf[p][q]), "f"(wf[p][q]));
#pragma unroll
                for (int j = 0; j < 4; j++)
                    asm("fma.rn.f32x2 %0, %1, %2, %0;"
                        : "+l"(acc[p][q][j]) : "l"(wp), "l"(xv[j]));
            }
    }

#pragma unroll
    for (int p = 0; p < 2; p++)
#pragma unroll
        for (int q = 0; q < 4; q++) {
            float o[8];
#pragma unroll
            for (int j = 0; j < 4; j++)
                asm("mov.b64 {%0, %1}, %2;" : "=f"(o[2 * j]), "=f"(o[2 * j + 1]) : "l"(acc[p][q][j]));
            float* yp = yout + ((size_t)(n * 2 + p)) * NODE_SZ + (r0 + q) * HEIGHT + h0;
            *(float4*)yp = make_float4(o[0], o[1], o[2], o[3]);
            if (h0 < 56)
                *(float4*)(yp + 4) = make_float4(o[4], o[5], o[6], o[7]);
        }
}

// ---------------- G0: gemm layer 0 from input x ------------------------------
__global__ __launch_bounds__(256, 2)
void gemm0_kernel(const float* __restrict__ x0) {
    extern __shared__ float sm[];
    int n = blockIdx.x, tid = threadIdx.x;
    const float* xn = x0 + (size_t)n * NODE_SZ;
#pragma unroll 4
    for (int i = tid; i < XS_SZ; i += 256) {
        int k = i >> 6, h = i & 63;
        sm[i] = (h < HEIGHT) ? xn[k * HEIGHT + h] : 0.f;
    }
    __syncthreads();
    gemm_body(sm, g_wt, g_y[0], n, tid);
}

// ---------------- F_l: edge(l) [+ gemm(l+1)] ---------------------------------
__global__ __launch_bounds__(256, 2)
void fused_kernel(const float* __restrict__ ea,
                  const float* __restrict__ lng,
                  const float* __restrict__ lnb,
                  const int* __restrict__ ei,
                  float* __restrict__ dout, int l) {
    extern __shared__ float sm[];
    float* es_all = sm + ES_OFF;
    __shared__ float red[16];

    int n = blockIdx.x, tid = threadIdx.x;
    const float* gl = lng + l * NODE_SZ;
    const float* bl = lnb + l * NODE_SZ;
    const float* ybuf = g_y[l & 1];
    int deg = g_deg[n];

    // prefetch edge 0's yb into ring slot 0
    {
        int s0 = ei[g_nbr[n * 16]];
        prefetch_node(sm, ybuf + (size_t)(2 * s0 + 1) * NODE_SZ, tid);
    }

    // ya + acc registers (overlaps with prefetch latency)
    const float* yan = ybuf + (size_t)(2 * n) * NODE_SZ;
    float ya[30], acc[30];
#pragma unroll
    for (int it = 0; it < 30; it++) {
        ya[it] = yan[tid + (it << 8)];
        acc[it] = 0.f;
    }
    // edge scalars for all edges
    for (int idx = tid; idx < deg * CCH; idx += 256) {
        int j = idx >> 7, c = idx & 127;
        int e = g_nbr[n * 16 + j];
        const float* Mp = g_M + l * (CCH * 6) + c * 6;
        const float* eap = ea + e * 5;
        es_all[idx] = fmaf(Mp[0], eap[0], fmaf(Mp[1], eap[1], fmaf(Mp[2], eap[2],
                      fmaf(Mp[3], eap[3], fmaf(Mp[4], eap[4], Mp[5])))));
    }

    int bj = 0;
    for (int j = 0; j < deg; j++) {
        if (j + 1 < deg) {
            int s1i = ei[g_nbr[n * 16 + j + 1]];
            int bn = bj + 1; if (bn == 3) bn = 0;
            prefetch_node(sm + bn * NODE_SZ, ybuf + (size_t)(2 * s1i + 1) * NODE_SZ, tid);
            asm volatile("cp.async.wait_group 1;");
        } else {
            asm volatile("cp.async.wait_group 0;");
        }
        __syncthreads();   // BARRIER_A: ring slot bj (+ es_all on j==0) visible

        const float* bf = sm + bj * NODE_SZ;
        const float* esj = es_all + j * CCH;
        float s1 = 0.f, s2 = 0.f;
#pragma unroll
        for (int it = 0; it < 30; it++) {
            int i = tid + (it << 8);
            float v = ya[it] + bf[i] + esj[i / HEIGHT];
            s1 += v;
            s2 += v * v;
        }
#pragma unroll
        for (int o = 16; o; o >>= 1) {
            s1 += __shfl_xor_sync(0xffffffffu, s1, o);
            s2 += __shfl_xor_sync(0xffffffffu, s2, o);
        }
        if ((tid & 31) == 0) { red[tid >> 5] = s1; red[8 + (tid >> 5)] = s2; }
        __syncthreads();   // BARRIER_B
        float a = 0.f, b2 = 0.f;
#pragma unroll
        for (int w = 0; w < 8; w++) { a += red[w]; b2 += red[8 + w]; }
        float mu = a * (1.f / (float)NODE_SZ);
        float rs = rsqrtf(b2 * (1.f / (float)NODE_SZ) - mu * mu + 1e-5f);
#pragma unroll
        for (int it = 0; it < 30; it++) {
            int i = tid + (it << 8);
            float v = ya[it] + bf[i] + esj[i / HEIGHT];
            float o2 = (v - mu) * rs * gl[i] + bl[i];
            acc[it] += fmaxf(o2, 0.f);
        }
        bj++; if (bj == 3) bj = 0;
    }

    if (l == 3) {
        float* on = dout + (size_t)n * NODE_SZ;
#pragma unroll
        for (int it = 0; it < 30; it++)
            on[tid + (it << 8)] = acc[it];
        return;
    }

    // stage acc -> xs [k][64] (cols 60..63 zero), then gemm(l+1)
    __syncthreads();   // all ring reads done before xs overwrite
    float* xs = sm;
#pragma unroll
    for (int it = 0; it < 30; it++) {
        int i = tid + (it << 8);
        int k = i / HEIGHT, h = i - k * HEIGHT;
        xs[(k << 6) + h] = acc[it];
    }
    for (int p = tid; p < CCH * 4; p += 256)
        xs[((p >> 2) << 6) + 60 + (p & 3)] = 0.f;
    __syncthreads();
    gemm_body(xs, g_wt + (l + 1) * WT_SZ, g_y[(l + 1) & 1], n, tid);
}

// ---------------- launch -----------------------------------------------------
extern "C" void kernel_launch(void* const* d_in, const int* in_sizes, int n_in,
                              void* d_out, int out_size) {
    const float* x   = (const float*)d_in[0];
    const float* ea  = (const float*)d_in[1];
    const float* ew  = (const float*)d_in[2];
    const float* eb  = (const float*)d_in[3];
    const float* cw  = (const float*)d_in[4];
    const float* lng = (const float*)d_in[5];
    const float* lnb = (const float*)d_in[6];
    const int*   ei  = (const int*)d_in[7];
    float* out = (float*)d_out;
    int E = in_sizes[7] / 2;

    cudaFuncSetAttribute(gemm0_kernel, cudaFuncAttributeMaxDynamicSharedMemorySize, G0_SMEM);
    cudaFuncSetAttribute(fused_kernel, cudaFuncAttributeMaxDynamicSharedMemorySize, DYN_SMEM);

    setup_kernel<<<5, 384>>>(ei, E, cw, ew, eb);
    gemm0_kernel<<<N_NODES, 256, G0_SMEM>>>(x);
    for (int l = 0; l < N_LAYERS; l++)
        fused_kernel<<<N_NODES, 256, DYN_SMEM>>>(ea, lng, lnb, ei, out, l);
}

// round 6
// speedup vs baseline: 1.1485x; 1.1431x over previous
#include <cuda_runtime.h>

#define N_NODES 384
#define HEIGHT  60
#define CCH     128
#define N_LAYERS 4
#define NODE_SZ (CCH * HEIGHT)          // 7680 floats per node
#define WT_SZ   (CCH * 256)             // folded weights per layer
#define XS_SZ   (CCH * 64)              // 8192 floats (padded x tile)
#define ES_OFF  (3 * NODE_SZ)
#define DYN_F   (ES_OFF + 8 * CCH)
#define DYN_SMEM (DYN_F * 4)            // ~94 KB (edge kernel)

// ---------------- device scratch ----------------
__device__ __align__(16) float g_y[N_NODES * 2 * NODE_SZ];   // [n][a/b][c][h]
__device__ __align__(16) float g_xb[2][N_NODES * NODE_SZ];   // layer ping-pong
__device__ __align__(16) float g_wt[N_LAYERS * WT_SZ];       // [l][k][r]
__device__ float g_M[N_LAYERS * CCH * 6];
__device__ int   g_nbr[N_NODES * 16];
__device__ int   g_deg[N_NODES];

// ---------------- cp.async helpers ----------------
__device__ __forceinline__ void cp16(unsigned dst, const float* src) {
    asm volatile("cp.async.cg.shared.global [%0], [%1], 16;" :: "r"(dst), "l"(src));
}
__device__ __forceinline__ void prefetch_node(float* buf, const float* __restrict__ src,
                                              int tid, int nthr) {
    unsigned b = (unsigned)__cvta_generic_to_shared(buf);
    for (int i = tid; i < NODE_SZ / 4; i += nthr)
        cp16(b + i * 16, src + i * 4);
    asm volatile("cp.async.commit_group;");
}

// ---------------- setup: block 0 = CSR, blocks 1..4 = weight folding ----------
__global__ void setup_kernel(const int* __restrict__ ei, int E,
                             const float* __restrict__ conv_w,
                             const float* __restrict__ edge_w,
                             const float* __restrict__ edge_b) {
    int tid = threadIdx.x;
    if (blockIdx.x == 0) {
        int n = tid;
        if (n >= N_NODES) return;
        const int* dst = ei + E;
        int cnt = 0;
        for (int e = 0; e < E; e++) {
            if (dst[e] == n) {
                if (cnt < 8) g_nbr[n * 16 + cnt] = e;
                cnt++;
            }
        }
        g_deg[n] = cnt < 8 ? cnt : 8;
        return;
    }
    int l = blockIdx.x - 1;
    const float* cw = conv_w + l * (CCH * 3 * CCH);
    for (int i = tid; i < WT_SZ; i += 384) {
        int k = i >> 8, r = i & 255;
        float v;
        if (r < 128) v = cw[r * 384 + k] - cw[r * 384 + 128 + k];
        else         v = cw[(r - 128) * 384 + 128 + k];
        g_wt[l * WT_SZ + i] = v;
    }
    if (tid < CCH) {
        int c = tid;
        const float* cw3 = cw + c * 384 + 256;
        const float* ewl = edge_w + l * (CCH * 5);
        const float* ebl = edge_b + l * CCH;
        float m0 = 0.f, m1 = 0.f, m2 = 0.f, m3 = 0.f, m4 = 0.f, m5 = 0.f;
        for (int k = 0; k < CCH; k++) {
            float w = cw3[k];
            m0 += w * ewl[k * 5 + 0];
            m1 += w * ewl[k * 5 + 1];
            m2 += w * ewl[k * 5 + 2];
            m3 += w * ewl[k * 5 + 3];
            m4 += w * ewl[k * 5 + 4];
            m5 += w * ebl[k];
        }
        float* Mp = g_M + l * (CCH * 6) + c * 6;
        Mp[0] = m0; Mp[1] = m1; Mp[2] = m2; Mp[3] = m3; Mp[4] = m4; Mp[5] = m5;
    }
}

// ---------------- GEMM: y[n](256x60) = Wt(256x128) @ x[n](128x60) ------------
// 512 threads: wid 0..15 -> (part p = wid>>3, 8 h-cols h0 = (wid&7)*8);
// lane owns 4 consecutive rows (r0 = lane*4) -> weight LDG.128 coalesced.
__global__ __launch_bounds__(512, 2)
void gemm_kernel(const float* __restrict__ x0, int l) {
    __shared__ float xs[XS_SZ];   // 32 KB
    const float* xin = (l == 0) ? x0 : g_xb[(l + 1) & 1];
    const float* wt = g_wt + l * WT_SZ;
    int n = blockIdx.x, tid = threadIdx.x;
    const float* xn = xin + (size_t)n * NODE_SZ;

#pragma unroll 4
    for (int i = tid; i < XS_SZ; i += 512) {
        int k = i >> 6, h = i & 63;
        xs[i] = (h < HEIGHT) ? xn[k * HEIGHT + h] : 0.f;
    }
    __syncthreads();

    int lane = tid & 31, wid = tid >> 5;
    int p = wid >> 3, h0 = (wid & 7) << 3, r0 = lane << 2;
    const float* wbase = wt + p * 128 + r0;

    unsigned long long acc[4][4];
#pragma unroll
    for (int q = 0; q < 4; q++)
#pragma unroll
        for (int j = 0; j < 4; j++) acc[q][j] = 0ULL;

#pragma unroll 4
    for (int kk = 0; kk < CCH; kk++) {
        ulonglong2 x01 = *reinterpret_cast<const ulonglong2*>(xs + (kk << 6) + h0);
        ulonglong2 x23 = *reinterpret_cast<const ulonglong2*>(xs + (kk << 6) + h0 + 4);
        unsigned long long xv[4] = {x01.x, x01.y, x23.x, x23.y};
        float4 w = __ldg(reinterpret_cast<const float4*>(wbase + (kk << 8)));
        float wf[4] = {w.x, w.y, w.z, w.w};
#pragma unroll
        for (int q = 0; q < 4; q++) {
            unsigned long long wp;
            asm("mov.b64 %0, {%1, %2};" : "=l"(wp) : "f"(wf[q]), "f"(wf[q]));
#pragma unroll
            for (int j = 0; j < 4; j++)
                asm("fma.rn.f32x2 %0, %1, %2, %0;"
                    : "+l"(acc[q][j]) : "l"(wp), "l"(xv[j]));
        }
    }

#pragma unroll
    for (int q = 0; q < 4; q++) {
        float o[8];
#pragma unroll
        for (int j = 0; j < 4; j++)
            asm("mov.b64 {%0, %1}, %2;" : "=f"(o[2 * j]), "=f"(o[2 * j + 1]) : "l"(acc[q][j]));
        float* yp = g_y + ((size_t)(n * 2 + p)) * NODE_SZ + (r0 + q) * HEIGHT + h0;
        *(float4*)yp = make_float4(o[0], o[1], o[2], o[3]);
        if (h0 < 56)
            *(float4*)(yp + 4) = make_float4(o[4], o[5], o[6], o[7]);
    }
}

// ---------------- edge(l): per-dst CTA, 512 threads ---------------------------
__global__ __launch_bounds__(512, 2)
void edge_kernel(const float* __restrict__ ea,
                 const float* __restrict__ lng,
                 const float* __restrict__ lnb,
                 const int* __restrict__ ei,
                 float* __restrict__ dout, int l) {
    extern __shared__ float sm[];
    float* es_all = sm + ES_OFF;
    __shared__ float red[32];

    int n = blockIdx.x, tid = threadIdx.x;
    const float* gl = lng + l * NODE_SZ;
    const float* bl = lnb + l * NODE_SZ;
    float* xout = (l == 3) ? dout : g_xb[l & 1];
    int deg = g_deg[n];

    // prefetch edge 0's yb into ring slot 0
    {
        int s0 = ei[g_nbr[n * 16]];
        prefetch_node(sm, g_y + (size_t)(2 * s0 + 1) * NODE_SZ, tid, 512);
    }

    const float* yan = g_y + (size_t)(2 * n) * NODE_SZ;
    float ya[15], acc[15];
#pragma unroll
    for (int it = 0; it < 15; it++) {
        ya[it] = yan[tid + (it << 9)];
        acc[it] = 0.f;
    }
    for (int idx = tid; idx < deg * CCH; idx += 512) {
        int j = idx >> 7, c = idx & 127;
        int e = g_nbr[n * 16 + j];
        const float* Mp = g_M + l * (CCH * 6) + c * 6;
        const float* eap = ea + e * 5;
        es_all[idx] = fmaf(Mp[0], eap[0], fmaf(Mp[1], eap[1], fmaf(Mp[2], eap[2],
                      fmaf(Mp[3], eap[3], fmaf(Mp[4], eap[4], Mp[5])))));
    }

    int bj = 0;
    for (int j = 0; j < deg; j++) {
        if (j + 1 < deg) {
            int s1i = ei[g_nbr[n * 16 + j + 1]];
            int bn = bj + 1; if (bn == 3) bn = 0;
            prefetch_node(sm + bn * NODE_SZ, g_y + (size_t)(2 * s1i + 1) * NODE_SZ, tid, 512);
            asm volatile("cp.async.wait_group 1;");
        } else {
            asm volatile("cp.async.wait_group 0;");
        }
        __syncthreads();   // slot bj (+ es_all on j==0) visible; ring safety (3 slots)

        const float* bf = sm + bj * NODE_SZ;
        const float* esj = es_all + j * CCH;
        float s1 = 0.f, s2 = 0.f;
#pragma unroll
        for (int it = 0; it < 15; it++) {
            int i = tid + (it << 9);
            float v = ya[it] + bf[i] + esj[i / HEIGHT];
            s1 += v;
            s2 += v * v;
        }
#pragma unroll
        for (int o = 16; o; o >>= 1) {
            s1 += __shfl_xor_sync(0xffffffffu, s1, o);
            s2 += __shfl_xor_sync(0xffffffffu, s2, o);
        }
        if ((tid & 31) == 0) { red[tid >> 5] = s1; red[16 + (tid >> 5)] = s2; }
        __syncthreads();
        float a = 0.f, b2 = 0.f;
#pragma unroll
        for (int w = 0; w < 16; w++) { a += red[w]; b2 += red[16 + w]; }
        float mu = a * (1.f / (float)NODE_SZ);
        float rs = rsqrtf(b2 * (1.f / (float)NODE_SZ) - mu * mu + 1e-5f);
#pragma unroll
        for (int it = 0; it < 15; it++) {
            int i = tid + (it << 9);
            float v = ya[it] + bf[i] + esj[i / HEIGHT];
            float o2 = (v - mu) * rs * gl[i] + bl[i];
            acc[it] += fmaxf(o2, 0.f);
        }
        bj++; if (bj == 3) bj = 0;
    }

    float* on = xout + (size_t)n * NODE_SZ;
#pragma unroll
    for (int it = 0; it < 15; it++)
        on[tid + (it << 9)] = acc[it];
}

// ---------------- launch -----------------------------------------------------
extern "C" void kernel_launch(void* const* d_in, const int* in_sizes, int n_in,
                              void* d_out, int out_size) {
    const float* x   = (const float*)d_in[0];
    const float* ea  = (const float*)d_in[1];
    const float* ew  = (const float*)d_in[2];
    const float* eb  = (const float*)d_in[3];
    const float* cw  = (const float*)d_in[4];
    const float* lng = (const float*)d_in[5];
    const float* lnb = (const float*)d_in[6];
    const int*   ei  = (const int*)d_in[7];
    float* out = (float*)d_out;
    int E = in_sizes[7] / 2;

    cudaFuncSetAttribute(edge_kernel, cudaFuncAttributeMaxDynamicSharedMemorySize, DYN_SMEM);

    setup_kernel<<<5, 384>>>(ei, E, cw, ew, eb);
    for (int l = 0; l < N_LAYERS; l++) {
        gemm_kernel<<<N_NODES, 512>>>(x, l);
        edge_kernel<<<N_NODES, 512, DYN_SMEM>>>(ea, lng, lnb, ei, out, l);
    }
}